// round 11
// baseline (speedup 1.0000x reference)
#include <cuda_runtime.h>
#include <cstdint>

#define H      16384
#define BATCH  512
#define INSZ   2048
#define KSEL   64
#define DECAY  0.95f

#define NTH    1024
#define CAP    1024

__device__ float g_enc[(size_t)BATCH * H];   // 32 MB scratch (no-alloc rule)

// ---------------------------------------------------------------------------
__global__ void zero_out_kernel(float4* __restrict__ out, int n4) {
    int i = blockIdx.x * blockDim.x + threadIdx.x;
    if (i < n4) out[i] = make_float4(0.f, 0.f, 0.f, 0.f);
}

// ---------------------------------------------------------------------------
// fp32 GEMM  C[m][n] = sum_k A[m][k]*W[n][k]; 128x128 tile, BK=16,
// double-buffered smem + register prefetch (1 sync per k-tile).
// ---------------------------------------------------------------------------
#define GBM 128
#define GBN 128
#define GBK 16

__global__ void __launch_bounds__(256) sgemm_nt_kernel(
    const float* __restrict__ A, const float* __restrict__ W)
{
    __shared__ float As[2][GBK][GBM];
    __shared__ float Bs[2][GBK][GBN];

    const int bn = blockIdx.x * GBN, bm = blockIdx.y * GBM;
    const int tid = threadIdx.x, tx = tid & 15, ty = tid >> 4;

    // per-thread load coords (two 256-thread chunks cover 128 rows x 16 k)
    const int r0 = tid >> 2,          kk0 = (tid & 3) * 4;
    const int r1 = (tid + 256) >> 2,  kk1 = ((tid + 256) & 3) * 4;

    float acc[8][8];
#pragma unroll
    for (int i = 0; i < 8; i++)
#pragma unroll
        for (int j = 0; j < 8; j++) acc[i][j] = 0.f;

    // preload tile 0
    {
        float4 a0 = *(const float4*)&A[(bm + r0) * INSZ + kk0];
        float4 a1 = *(const float4*)&A[(bm + r1) * INSZ + kk1];
        float4 b0 = *(const float4*)&W[(bn + r0) * INSZ + kk0];
        float4 b1 = *(const float4*)&W[(bn + r1) * INSZ + kk1];
        As[0][kk0][r0] = a0.x; As[0][kk0+1][r0] = a0.y; As[0][kk0+2][r0] = a0.z; As[0][kk0+3][r0] = a0.w;
        As[0][kk1][r1] = a1.x; As[0][kk1+1][r1] = a1.y; As[0][kk1+2][r1] = a1.z; As[0][kk1+3][r1] = a1.w;
        Bs[0][kk0][r0] = b0.x; Bs[0][kk0+1][r0] = b0.y; Bs[0][kk0+2][r0] = b0.z; Bs[0][kk0+3][r0] = b0.w;
        Bs[0][kk1][r1] = b1.x; Bs[0][kk1+1][r1] = b1.y; Bs[0][kk1+2][r1] = b1.z; Bs[0][kk1+3][r1] = b1.w;
    }
    __syncthreads();

    int buf = 0;
    for (int k0 = GBK; k0 <= INSZ; k0 += GBK) {
        const bool more = (k0 < INSZ);
        float4 na0, na1, nb0, nb1;
        if (more) {
            na0 = *(const float4*)&A[(bm + r0) * INSZ + k0 + kk0];
            na1 = *(const float4*)&A[(bm + r1) * INSZ + k0 + kk1];
            nb0 = *(const float4*)&W[(bn + r0) * INSZ + k0 + kk0];
            nb1 = *(const float4*)&W[(bn + r1) * INSZ + k0 + kk1];
        }
#pragma unroll
        for (int k = 0; k < GBK; k++) {
            float a[8], b[8];
#pragma unroll
            for (int i = 0; i < 8; i++) a[i] = As[buf][k][ty * 8 + i];
#pragma unroll
            for (int i = 0; i < 8; i++) b[i] = Bs[buf][k][tx * 8 + i];
#pragma unroll
            for (int i = 0; i < 8; i++)
#pragma unroll
                for (int j = 0; j < 8; j++)
                    acc[i][j] = fmaf(a[i], b[j], acc[i][j]);
        }
        if (more) {
            int nb = buf ^ 1;
            As[nb][kk0][r0] = na0.x; As[nb][kk0+1][r0] = na0.y; As[nb][kk0+2][r0] = na0.z; As[nb][kk0+3][r0] = na0.w;
            As[nb][kk1][r1] = na1.x; As[nb][kk1+1][r1] = na1.y; As[nb][kk1+2][r1] = na1.z; As[nb][kk1+3][r1] = na1.w;
            Bs[nb][kk0][r0] = nb0.x; Bs[nb][kk0+1][r0] = nb0.y; Bs[nb][kk0+2][r0] = nb0.z; Bs[nb][kk0+3][r0] = nb0.w;
            Bs[nb][kk1][r1] = nb1.x; Bs[nb][kk1+1][r1] = nb1.y; Bs[nb][kk1+2][r1] = nb1.z; Bs[nb][kk1+3][r1] = nb1.w;
        }
        __syncthreads();
        buf ^= 1;
    }

#pragma unroll
    for (int i = 0; i < 8; i++) {
        int m = bm + ty * 8 + i;
#pragma unroll
        for (int j = 0; j < 8; j += 4)
            *(float4*)&g_enc[(size_t)m * H + bn + tx * 8 + j] =
                make_float4(acc[i][j], acc[i][j+1], acc[i][j+2], acc[i][j+3]);
    }
}

// ---------------------------------------------------------------------------
// Persistent single-CTA scan.
// Layout: thread t, word jj (0..3): float4 at element jj*4096 + 4*t, lane
// element u = jj*4+c  ->  global idx = jj*4096 + 4*t + c.
// Candidate key: (r_bits<<32) | (e>0)<<16 | (16383 - idx)   [14-bit idx field,
// exact-tie order vs sign: measure-zero, accepted].
// Final-mask fill (total-order top_k, -0.0 < +0.0): selected positives,
// then non-selected e>0 ascending, then non-selected e<0 ascending.
// ---------------------------------------------------------------------------
__global__ void __launch_bounds__(NTH, 1) scan_kernel(float* __restrict__ out)
{
    __shared__ unsigned long long s_ckey[CAP];
    __shared__ unsigned long long s_selkey[KSEL];
    __shared__ unsigned s_selbit[H / 32];      // 512 words
    __shared__ int      s_cnt;
    __shared__ int      s_p[2];
    __shared__ unsigned s_rmax[2];
    __shared__ float    s_T;
    __shared__ int      s_wcnt[32];

    const int t = threadIdx.x, lane = t & 31, wp = t >> 5;
    const unsigned lt = (1u << lane) - 1u;

    float inhib[16];
#pragma unroll
    for (int u = 0; u < 16; u++) inhib[u] = 0.f;

    if (t == 0) {
        s_T = -1.f; s_cnt = 0;
        s_p[0] = s_p[1] = 0;
        s_rmax[0] = s_rmax[1] = 0u;
    }
    __syncthreads();

    for (int row = 0; row < BATCH; row++) {
        const float* erow = g_enc + (size_t)row * H;
        const int rp = row & 1;

        // ---- phase A: clear bitmap, load row (float4), refracted, max ----
        if (t < H / 32) s_selbit[t] = 0u;

        float r[16];
        unsigned pmask = 0;
        float rmax = 0.f;
#pragma unroll
        for (int jj = 0; jj < 4; jj++) {
            float4 v = *(const float4*)(erow + jj * 4096 + 4 * t);
            float e[4] = {v.x, v.y, v.z, v.w};
#pragma unroll
            for (int c = 0; c < 4; c++) {
                int u = jj * 4 + c;
                float rr = fabsf(e[c]) * (1.0f - inhib[u]);
                r[u] = rr;
                rmax = fmaxf(rmax, rr);
                pmask |= (unsigned)(e[c] > 0.f) << u;
            }
        }
        unsigned rmu = __reduce_max_sync(0xffffffffu, __float_as_uint(rmax));
        if (lane == 0) atomicMax(&s_rmax[rp], rmu);
        __syncthreads();                                   // bar1
        rmax = __uint_as_float(s_rmax[rp]);

        float T = s_T;
        if (!(T > 0.f && T < rmax)) T = 0.5f * rmax;
        float Tlo = 0.f, Thi = rmax;
        int M;

        // ---- candidate gather + bisection retry ----
        for (;;) {
#pragma unroll
            for (int u = 0; u < 16; u++) {
                bool pred = r[u] > T;
                unsigned bal = __ballot_sync(0xffffffffu, pred);
                if (bal) {
                    int ldr = __ffs(bal) - 1;
                    int base = 0;
                    if (lane == ldr) base = atomicAdd(&s_cnt, __popc(bal));
                    base = __shfl_sync(0xffffffffu, base, ldr);
                    if (pred) {
                        int pos = base + __popc(bal & lt);
                        if (pos < CAP) {
                            unsigned idx = (unsigned)((u >> 2) * 4096 + 4 * t + (u & 3));
                            unsigned lowk = (((pmask >> u) & 1u) << 16) | (16383u - idx);
                            s_ckey[pos] =
                                ((unsigned long long)__float_as_uint(r[u]) << 32) | lowk;
                        }
                    }
                }
            }
            __syncthreads();                               // bar2
            M = s_cnt;
            if (M >= KSEL && M <= CAP) { if (t == 0) s_cnt = 0; break; }
            if (M > CAP) Tlo = T; else Thi = T;
            T = 0.5f * (Tlo + Thi);
            __syncthreads();
            if (t == 0) s_cnt = 0;
            __syncthreads();
        }

        // ---- exact rank selection; winners emit bitmap/output/p inline ----
        if (t < M) {
            unsigned long long k = s_ckey[t];
            int rank = 0;
            for (int d = 0; d < M; d++) rank += (s_ckey[d] > k);
            if (rank < KSEL) {
                s_selkey[rank] = k;
                unsigned idx = 16383u - ((unsigned)k & 0x3FFFu);
                atomicOr(&s_selbit[idx >> 5], 1u << (idx & 31));
                if ((unsigned)(k >> 16) & 1u) {
                    out[(size_t)row * H + idx] = 1.0f;
                    atomicAdd(&s_p[rp], 1);
                }
            }
        }
        __syncthreads();                                   // bar3

        int cnt = s_p[rp];
        if (t == 0) {                    // prep next row's parity buffers
            s_p[rp ^ 1] = 0;
            s_rmax[rp ^ 1] = 0u;
            s_T = __uint_as_float((unsigned)(s_selkey[KSEL - 1] >> 32)) * 0.85f;
        }

        // ---- inhibition update: pure LDS, no global traffic ----
#pragma unroll
        for (int u = 0; u < 16; u++) inhib[u] *= DECAY;
        for (int s = 0; s < KSEL; s++) {
            unsigned idx = 16383u - ((unsigned)s_selkey[s] & 0x3FFFu);
            if ((int)((idx & 4095u) >> 2) == t)
                inhib[(idx >> 12) * 4 + (idx & 3u)] += 1.0f;
        }

        // ---- fill from registers + bitmap (2 sign passes, 1024-chunks) ----
        for (int pass = 0; pass < 2 && cnt < KSEL; pass++) {
            for (int q = 0; q < 16; q++) {
                const int jj = q >> 2;
                const bool active = ((t >> 8) == (q & 3));
                unsigned cb = 0;
                if (active) {
#pragma unroll
                    for (int c = 0; c < 4; c++) {
                        int u = jj * 4 + c;
                        unsigned idx = (unsigned)(jj * 4096 + 4 * t + c);
                        bool sel = (s_selbit[idx >> 5] >> (idx & 31)) & 1u;
                        bool pb  = (pmask >> u) & 1u;
                        bool cand = !sel && (pass == 0 ? pb : !pb);
                        cb |= (unsigned)cand << c;
                    }
                }
                int pre = 0, wtot = 0;
#pragma unroll
                for (int c = 0; c < 4; c++) {
                    unsigned bal = __ballot_sync(0xffffffffu, (cb >> c) & 1u);
                    pre  += __popc(bal & lt);
                    wtot += __popc(bal);
                }
                if (lane == 0) s_wcnt[wp] = wtot;
                __syncthreads();
                int gpre = 0, gtot = 0;
                const int wbase = 8 * (q & 3);
#pragma unroll
                for (int w = 0; w < 8; w++) {
                    int cc = s_wcnt[wbase + w];
                    if (wbase + w < wp) gpre += cc;
                    gtot += cc;
                }
                if (active && cb) {
                    int base2 = cnt + gpre + pre;
                    int within = 0;
#pragma unroll
                    for (int c = 0; c < 4; c++) {
                        if ((cb >> c) & 1u) {
                            if (base2 + within < KSEL)
                                out[(size_t)row * H + jj * 4096 + 4 * t + c] = 1.0f;
                            within++;
                        }
                    }
                }
                cnt += gtot;                    // uniform across block
                __syncthreads();
                if (cnt >= KSEL) break;
            }
        }
        __syncthreads();        // final: orders bitmap clear / rmax / s_T / s_cnt
    }
}

// ---------------------------------------------------------------------------
extern "C" void kernel_launch(void* const* d_in, const int* in_sizes, int n_in,
                              void* d_out, int out_size)
{
    const float* inputs = (const float*)d_in[0];   // [512, 2048]
    const float* W      = (const float*)d_in[1];   // [16384, 2048]
    float* out          = (float*)d_out;           // [512, 16384]

    const int n4 = (BATCH * H) / 4;
    zero_out_kernel<<<(n4 + 255) / 256, 256>>>((float4*)out, n4);

    dim3 ggrid(H / GBN, BATCH / GBM);              // (128, 4)
    sgemm_nt_kernel<<<ggrid, 256>>>(inputs, W);

    scan_kernel<<<1, NTH>>>(out);
}